// round 15
// baseline (speedup 1.0000x reference)
#include <cuda_runtime.h>

#define MM 361
#define LL 359

#define X_ELEMS  33177600   // 8*8*2*360*720
#define W_ELEMS  93311280   // 2*361*359*360

// ============================================================================
// Single fused kernel. grid = (361 m, 16 b-groups), block = 256 (8 warps).
// d_out = 16,588,672 float32 = REAL PART of the complex output, layout
// (8,8,2,359,361) flattened. All stores guarded by runtime out_size.
//
// Real parts need only 4 contractions:
//   o0r = P0[ar] - P1[bi]        (P_d[v] = sum_k w_d[m,l,k] * v[k])
//   o1r = -P1[ai] - P0[br]
// ============================================================================
__global__ void __launch_bounds__(256) rv_fused(const float* __restrict__ x,
                                                const float* __restrict__ w,
                                                float* __restrict__ out,
                                                long long out_cap_f) {
    const int m    = blockIdx.x;          // 0..360
    const int bg   = blockIdx.y;          // 0..15
    const int tid  = threadIdx.x;
    const int lane = tid & 31;
    const int wid  = tid >> 5;

    __shared__ float twc[368];            // s*cos(2pi m n/720), n = 0..360
    __shared__ float tws[368];            // -s*sin(2pi m n/720), valid n = 1..359
    __shared__ float xf[4][4][360];       // [comp][bl][k], comp 0=ar 1=ai 2=br 3=bi

    // ---- phase 0: twiddles. angle = pi*p/360, p = (m*n) mod 720 (exact int) ----
    {
        const float s  = 8.7266462599716478846e-3f;   // 2*pi/720
        const float a0 = 8.7266462599716478846e-3f;   // pi/360
        for (int n = tid; n < 361; n += 256) {
            int p = (m * n) % 720;
            float sn, cs;
            __sincosf(a0 * (float)p, &sn, &cs);       // MUFU, no libdevice
            twc[n] = s * cs;
            tws[n] = -s * sn;
        }
    }
    __syncthreads();

    // ---- phase 1: folded DFT. 360 k * 4 bl * 2 c = 2880 tasks, warp each ----
    for (int t = wid; t < 2880; t += 8) {
        int k  = t % 360;
        int r  = t / 360;
        int bl = r & 3;
        int c  = r >> 2;
        int b  = bg * 4 + bl;
        const float* row = x + ((size_t)((b * 2 + c) * 360 + k)) * 720;

        float sR = 0.f, sI = 0.f;
        for (int n = lane; n < 361; n += 32) {
            float xn = row[n];
            if (n == 0 || n == 360) {
                sR += twc[n] * xn;
            } else {
                float xr = row[720 - n];
                sR += twc[n] * (xn + xr);
                sI += tws[n] * (xn - xr);
            }
        }
#pragma unroll
        for (int o = 16; o > 0; o >>= 1) {
            sR += __shfl_xor_sync(0xffffffffu, sR, o);
            sI += __shfl_xor_sync(0xffffffffu, sI, o);
        }
        if (lane == 0) {
            xf[2 * c][bl][k]     = sR;
            xf[2 * c + 1][bl][k] = sI;
        }
    }
    __syncthreads();

    // ---- phase 2: 4 contractions over k -> real parts only; GUARDED stores ----
    const float* w0 = w + (size_t)m * LL * 360;           // weights[0][m]
    const float* w1 = w + (size_t)(MM + m) * LL * 360;    // weights[1][m]
    const int bl = tid & 3;
    const int lt = tid >> 2;
    const int b  = bg * 4 + bl;

    for (int l = lt; l < LL; l += 64) {
        const float* wr0 = w0 + (size_t)l * 360;
        const float* wr1 = w1 + (size_t)l * 360;
        float p0ar = 0.f, p0br = 0.f, p1ai = 0.f, p1bi = 0.f;
        for (int k = 0; k < 360; k++) {
            float a0 = wr0[k];
            float a1 = wr1[k];
            p0ar += a0 * xf[0][bl][k];   // P0[ar]
            p0br += a0 * xf[2][bl][k];   // P0[br]
            p1ai += a1 * xf[1][bl][k];   // P1[ai]
            p1bi += a1 * xf[3][bl][k];   // P1[bi]
        }
        float o0r =  p0ar - p1bi;
        float o1r = -p1ai - p0br;
        long long i0 = ((long long)(b * 2 + 0) * LL + l) * MM + m;
        long long i1 = ((long long)(b * 2 + 1) * LL + l) * MM + m;
        if (i0 < out_cap_f) out[i0] = o0r;
        if (i1 < out_cap_f) out[i1] = o1r;
    }
}

// ============================================================================
// Launch: gate inputs on exact element counts; out_size = float capacity.
// ============================================================================
extern "C" void kernel_launch(void* const* d_in, const int* in_sizes, int n_in,
                              void* d_out, int out_size) {
    if (n_in < 2 || d_in == nullptr || d_out == nullptr) return;

    int xi = -1, wi = -1;
    for (int i = 0; i < n_in; i++) {
        if (in_sizes[i] == X_ELEMS && xi < 0) xi = i;
        if (in_sizes[i] == W_ELEMS && wi < 0) wi = i;
    }
    if (xi < 0 || wi < 0 || xi == wi) return;   // unexpected shapes: fail clean

    const float* x = (const float*)d_in[xi];
    const float* w = (const float*)d_in[wi];
    if (x == nullptr || w == nullptr) return;

    long long out_cap_f = (long long)out_size;
    if (out_cap_f < 0) out_cap_f = 0;

    dim3 grid(361, 16);
    rv_fused<<<grid, 256>>>(x, w, (float*)d_out, out_cap_f);
}

// round 16
// speedup vs baseline: 7.6424x; 7.6424x over previous
#include <cuda_runtime.h>

#define MM 361
#define LL 359
#define MPAD 384

#define X_ELEMS  33177600   // 8*8*2*360*720
#define W_ELEMS  93311280   // 2*361*359*360

// ---------------- device scratch (statics are safe; crashes were out-OOB) -----
__device__ float g_ct[361 * MPAD];           // s*cos(2pi m n/720), row n
__device__ float g_st[359 * MPAD];           // -s*sin(2pi m n/720), row n-1
__device__ float g_xf[361u * 360u * 256u];   // [m][k][comp*64+b] 0=ar 1=ai 2=br 3=bi

// ---------------- twiddle tables (MUFU only) -----------------------------------
__global__ void __launch_bounds__(256) k_tables() {
    int id = blockIdx.x * blockDim.x + threadIdx.x;
    const float s  = 8.7266462599716478846e-3f;   // 2*pi/720
    const float a0 = 8.7266462599716478846e-3f;   // pi/360
    if (id < 361 * MPAD) {
        int n = id / MPAD, m = id % MPAD;
        float v = 0.f;
        if (m < 361) {
            int p = (m * n) % 720;
            float sn, cs; __sincosf(a0 * (float)p, &sn, &cs);
            v = s * cs;
        }
        g_ct[id] = v;
    } else {
        int id2 = id - 361 * MPAD;
        if (id2 < 359 * MPAD) {
            int n = id2 / MPAD + 1, m = id2 % MPAD;
            float v = 0.f;
            if (m < 361) {
                int p = (m * n) % 720;
                float sn, cs; __sincosf(a0 * (float)p, &sn, &cs);
                v = -s * sn;
            }
            g_st[id2] = v;
        }
    }
}

// ---------------- stage 1: folded DFT as GEMM, x read directly ------------------
// grid (6 m-tiles of 64, 720 (k,c)). block 256 = 16 m-grp x 16 b-grp, 4m x 4b tile.
__global__ void __launch_bounds__(256) k_dft(const float* __restrict__ x) {
    const int mt = blockIdx.x;
    const int ck = blockIdx.y;
    const int c = ck & 1, k = ck >> 1;
    const int tid = threadIdx.x;
    const int tm = tid >> 4, tb = tid & 15;
    const int m_off = tm * 4, b_off = tb * 4;
    const int m0 = mt * 64;
    const int lane = tid & 31;
    const int wrp  = tid >> 5;

    __shared__ float es[32][68];   // [n][b]; 68: pad for banks + float4 align
    __shared__ float ts[32][64];   // [n][m]

    float aR[4][4], aI[4][4];
#pragma unroll
    for (int i = 0; i < 4; i++)
#pragma unroll
        for (int j = 0; j < 4; j++) { aR[i][j] = 0.f; aI[i][j] = 0.f; }

    // ---- cos/even pass: n = 0..360 ----
    for (int n0 = 0; n0 < 361; n0 += 32) {
#pragma unroll
        for (int j = 0; j < 8; j++) {
            int cb = wrp + j * 8;
            int n  = n0 + lane;
            const float* row = x + ((size_t)((cb * 2 + c) * 360 + k)) * 720;
            float v = 0.f;
            if (n < 361) {
                float xn = row[n];
                float xr = (n >= 1 && n <= 359) ? row[720 - n] : 0.f;
                v = xn + xr;
            }
            es[lane][cb] = v;
        }
#pragma unroll
        for (int j = 0; j < 8; j++) {
            int i = tid + j * 256;
            int nn = i >> 6, cb = i & 63;
            int n  = n0 + nn;
            ts[nn][cb] = (n < 361) ? g_ct[n * MPAD + m0 + cb] : 0.f;
        }
        __syncthreads();
#pragma unroll
        for (int nn = 0; nn < 32; nn++) {
            float e0 = es[nn][b_off + 0], e1 = es[nn][b_off + 1];
            float e2 = es[nn][b_off + 2], e3 = es[nn][b_off + 3];
            float t0 = ts[nn][m_off + 0], t1 = ts[nn][m_off + 1];
            float t2 = ts[nn][m_off + 2], t3 = ts[nn][m_off + 3];
            aR[0][0] += t0 * e0; aR[0][1] += t0 * e1; aR[0][2] += t0 * e2; aR[0][3] += t0 * e3;
            aR[1][0] += t1 * e0; aR[1][1] += t1 * e1; aR[1][2] += t1 * e2; aR[1][3] += t1 * e3;
            aR[2][0] += t2 * e0; aR[2][1] += t2 * e1; aR[2][2] += t2 * e2; aR[2][3] += t2 * e3;
            aR[3][0] += t3 * e0; aR[3][1] += t3 * e1; aR[3][2] += t3 * e2; aR[3][3] += t3 * e3;
        }
        __syncthreads();
    }

    // ---- sin/odd pass: n = np+1, np = 0..358 ----
    for (int n0 = 0; n0 < 359; n0 += 32) {
#pragma unroll
        for (int j = 0; j < 8; j++) {
            int cb = wrp + j * 8;
            int np = n0 + lane;
            const float* row = x + ((size_t)((cb * 2 + c) * 360 + k)) * 720;
            float v = 0.f;
            if (np < 359) v = row[np + 1] - row[719 - np];
            es[lane][cb] = v;
        }
#pragma unroll
        for (int j = 0; j < 8; j++) {
            int i = tid + j * 256;
            int nn = i >> 6, cb = i & 63;
            int np = n0 + nn;
            ts[nn][cb] = (np < 359) ? g_st[np * MPAD + m0 + cb] : 0.f;
        }
        __syncthreads();
#pragma unroll
        for (int nn = 0; nn < 32; nn++) {
            float e0 = es[nn][b_off + 0], e1 = es[nn][b_off + 1];
            float e2 = es[nn][b_off + 2], e3 = es[nn][b_off + 3];
            float t0 = ts[nn][m_off + 0], t1 = ts[nn][m_off + 1];
            float t2 = ts[nn][m_off + 2], t3 = ts[nn][m_off + 3];
            aI[0][0] += t0 * e0; aI[0][1] += t0 * e1; aI[0][2] += t0 * e2; aI[0][3] += t0 * e3;
            aI[1][0] += t1 * e0; aI[1][1] += t1 * e1; aI[1][2] += t1 * e2; aI[1][3] += t1 * e3;
            aI[2][0] += t2 * e0; aI[2][1] += t2 * e1; aI[2][2] += t2 * e2; aI[2][3] += t2 * e3;
            aI[3][0] += t3 * e0; aI[3][1] += t3 * e1; aI[3][2] += t3 * e2; aI[3][3] += t3 * e3;
        }
        __syncthreads();
    }

    const int cr = 2 * c, ci = 2 * c + 1;
#pragma unroll
    for (int i = 0; i < 4; i++) {
        int m = m0 + m_off + i;
        if (m < 361) {
            float* dst = g_xf + ((size_t)m * 360 + k) * 256;
#pragma unroll
            for (int j = 0; j < 4; j++) {
                dst[cr * 64 + b_off + j] = aR[i][j];
                dst[ci * 64 + b_off + j] = aI[i][j];
            }
        }
    }
}

// ---------------- stage 2: per-m GEMM over k, real-only combine -----------------
// grid (361 m, 6 l-tiles of 64). block 256 = 16 tl x 16 tb.
// thread: 4 l x 4 b x 4 partials (p0ar,p0br,p1ai,p1bi). k chunks of 24 (exact).
__global__ void __launch_bounds__(256) k_sht(const float* __restrict__ w,
                                             float* __restrict__ out,
                                             long long out_cap) {
    const int m  = blockIdx.x;
    const int l0 = blockIdx.y * 64;
    const int tid = threadIdx.x;
    const int tl = tid >> 4, tb = tid & 15;

    __shared__ float As[2][24][68];   // [d][k][l], padded
    __shared__ float Bs[24][256];     // [k][comp*64+b]

    float p0ar[4][4], p0br[4][4], p1ai[4][4], p1bi[4][4];
#pragma unroll
    for (int i = 0; i < 4; i++)
#pragma unroll
        for (int j = 0; j < 4; j++) {
            p0ar[i][j] = 0.f; p0br[i][j] = 0.f;
            p1ai[i][j] = 0.f; p1bi[i][j] = 0.f;
        }

    const size_t wpl = (size_t)LL * 360;               // 129240
    const float* w0 = w + (size_t)m * wpl;
    const float* w1 = w + (size_t)(MM + m) * wpl;
    const float* Bg = g_xf + (size_t)m * 360 * 256;

    for (int k0 = 0; k0 < 360; k0 += 24) {
        // As: 2*24*64 floats = 768 float4, 3 per thread. transpose to [k][l].
#pragma unroll
        for (int q = 0; q < 3; q++) {
            int idx = tid + q * 256;        // 0..767
            int d   = idx / 384;
            int r   = idx - d * 384;        // 0..383
            int li  = r / 6;                // 0..63
            int kq  = r - li * 6;           // 0..5
            int l   = l0 + li;
            float4 v = make_float4(0.f, 0.f, 0.f, 0.f);
            if (l < LL) {
                const float* src = (d ? w1 : w0) + (size_t)l * 360 + k0 + kq * 4;
                v = *(const float4*)src;    // 16B-aligned: k0%24==0, kq*4, l*360%4==0
            }
            As[d][kq * 4 + 0][li] = v.x;
            As[d][kq * 4 + 1][li] = v.y;
            As[d][kq * 4 + 2][li] = v.z;
            As[d][kq * 4 + 3][li] = v.w;
        }
        // Bs: 24*256 floats = 1536 float4, 6 per thread, coalesced.
#pragma unroll
        for (int q = 0; q < 6; q++) {
            int fidx = tid + q * 256;       // 0..1535
            int kk   = fidx >> 6;           // 0..23
            int c4   = fidx & 63;           // float4 col
            float4 v = *(const float4*)&Bg[(size_t)(k0 + kk) * 256 + c4 * 4];
            *(float4*)&Bs[kk][c4 * 4] = v;
        }
        __syncthreads();

#pragma unroll
        for (int kk = 0; kk < 24; kk++) {
            float4 a0 = *(const float4*)&As[0][kk][tl * 4];
            float4 a1 = *(const float4*)&As[1][kk][tl * 4];
            float4 var = *(const float4*)&Bs[kk][tb * 4];
            float4 vai = *(const float4*)&Bs[kk][64  + tb * 4];
            float4 vbr = *(const float4*)&Bs[kk][128 + tb * 4];
            float4 vbi = *(const float4*)&Bs[kk][192 + tb * 4];
            const float a0v[4] = {a0.x, a0.y, a0.z, a0.w};
            const float a1v[4] = {a1.x, a1.y, a1.z, a1.w};
            const float arv[4] = {var.x, var.y, var.z, var.w};
            const float aiv[4] = {vai.x, vai.y, vai.z, vai.w};
            const float brv[4] = {vbr.x, vbr.y, vbr.z, vbr.w};
            const float biv[4] = {vbi.x, vbi.y, vbi.z, vbi.w};
#pragma unroll
            for (int i = 0; i < 4; i++) {
#pragma unroll
                for (int j = 0; j < 4; j++) {
                    p0ar[i][j] += a0v[i] * arv[j];
                    p0br[i][j] += a0v[i] * brv[j];
                    p1ai[i][j] += a1v[i] * aiv[j];
                    p1bi[i][j] += a1v[i] * biv[j];
                }
            }
        }
        __syncthreads();
    }

    // combine + store real parts: out[((b*2+ch)*359 + l)*361 + m]
#pragma unroll
    for (int i = 0; i < 4; i++) {
        int l = l0 + tl * 4 + i;
        if (l < LL) {
#pragma unroll
            for (int j = 0; j < 4; j++) {
                int b = tb * 4 + j;
                float o0r =  p0ar[i][j] - p1bi[i][j];
                float o1r = -p1ai[i][j] - p0br[i][j];
                long long i0 = ((long long)(b * 2 + 0) * LL + l) * MM + m;
                long long i1 = ((long long)(b * 2 + 1) * LL + l) * MM + m;
                if (i0 < out_cap) out[i0] = o0r;
                if (i1 < out_cap) out[i1] = o1r;
            }
        }
    }
}

// ---------------- launch ---------------------------------------------------------
extern "C" void kernel_launch(void* const* d_in, const int* in_sizes, int n_in,
                              void* d_out, int out_size) {
    if (n_in < 2 || d_in == nullptr || d_out == nullptr) return;

    int xi = -1, wi = -1;
    for (int i = 0; i < n_in; i++) {
        if (in_sizes[i] == X_ELEMS && xi < 0) xi = i;
        if (in_sizes[i] == W_ELEMS && wi < 0) wi = i;
    }
    if (xi < 0 || wi < 0 || xi == wi) return;

    const float* x = (const float*)d_in[xi];
    const float* w = (const float*)d_in[wi];
    if (x == nullptr || w == nullptr) return;

    long long out_cap = (long long)out_size;
    if (out_cap < 0) out_cap = 0;

    {
        int total = 361 * MPAD + 359 * MPAD;
        k_tables<<<(total + 255) / 256, 256>>>();
    }
    {
        dim3 g(6, 720);
        k_dft<<<g, 256>>>(x);
    }
    {
        dim3 g(361, 6);
        k_sht<<<g, 256>>>(w, (float*)d_out, out_cap);
    }
}